// round 16
// baseline (speedup 1.0000x reference)
#include <cuda_runtime.h>
#include <cstdint>

// BERTEmbedding: out[b,l,:] = token_table[seq[b,l],:]
//                           + mean_{g<cnt}(genre_table[gids[seq[b,l],g],:])
//                           + pos_table[l,:]
//
// R16: 256-bit (v8.b32) vector memory ops — one warp instruction moves 1024B,
// covering TWO embedding rows. Warp = 2 consecutive tokens: lanes 0..15 own
// token A (32B chunk per lane), lanes 16..31 own token B. Genre loops of the
// two tokens run fused with per-half predication (max(cA,cB) iterations).
// Token loads use ld.global.nc.L2::evict_last.v8.b32 (pin table in L2);
// stores use st.global.L2::cache_hint.v8.b32 with evict_first policy.

#define NUM_TOKENS (256 * 200)
#define SEQ_L 200
#define MAX_G 8
#define BLOCK_THREADS 256
#define WARPS_PER_BLOCK 8
#define GRID_BLOCKS (NUM_TOKENS / (2 * WARPS_PER_BLOCK))   // 3200

struct F8 { float v[8]; };

__device__ __forceinline__ F8 ldg_v8_evict_last(const float* p) {
    int r0,r1,r2,r3,r4,r5,r6,r7;
    asm volatile("ld.global.nc.L2::evict_last.v8.b32 {%0,%1,%2,%3,%4,%5,%6,%7}, [%8];"
                 : "=r"(r0),"=r"(r1),"=r"(r2),"=r"(r3),
                   "=r"(r4),"=r"(r5),"=r"(r6),"=r"(r7) : "l"(p));
    F8 f;
    f.v[0]=__int_as_float(r0); f.v[1]=__int_as_float(r1);
    f.v[2]=__int_as_float(r2); f.v[3]=__int_as_float(r3);
    f.v[4]=__int_as_float(r4); f.v[5]=__int_as_float(r5);
    f.v[6]=__int_as_float(r6); f.v[7]=__int_as_float(r7);
    return f;
}
__device__ __forceinline__ F8 ldg_v8(const float* p) {
    int r0,r1,r2,r3,r4,r5,r6,r7;
    asm volatile("ld.global.nc.v8.b32 {%0,%1,%2,%3,%4,%5,%6,%7}, [%8];"
                 : "=r"(r0),"=r"(r1),"=r"(r2),"=r"(r3),
                   "=r"(r4),"=r"(r5),"=r"(r6),"=r"(r7) : "l"(p));
    F8 f;
    f.v[0]=__int_as_float(r0); f.v[1]=__int_as_float(r1);
    f.v[2]=__int_as_float(r2); f.v[3]=__int_as_float(r3);
    f.v[4]=__int_as_float(r4); f.v[5]=__int_as_float(r5);
    f.v[6]=__int_as_float(r6); f.v[7]=__int_as_float(r7);
    return f;
}
__device__ __forceinline__ void stg_v8_evict_first(float* p, const F8& f, uint64_t pol) {
    asm volatile("st.global.L2::cache_hint.v8.b32 [%0], {%1,%2,%3,%4,%5,%6,%7,%8}, %9;"
                 :: "l"(p),
                    "r"(__float_as_int(f.v[0])), "r"(__float_as_int(f.v[1])),
                    "r"(__float_as_int(f.v[2])), "r"(__float_as_int(f.v[3])),
                    "r"(__float_as_int(f.v[4])), "r"(__float_as_int(f.v[5])),
                    "r"(__float_as_int(f.v[6])), "r"(__float_as_int(f.v[7])),
                    "l"(pol) : "memory");
}
__device__ __forceinline__ uint64_t mk_evict_first_policy() {
    uint64_t pol;
    asm("createpolicy.fractional.L2::evict_first.b64 %0, 1.0;" : "=l"(pol));
    return pol;
}

__constant__ float c_inv[9] = {
    0.0f, 1.0f, 0.5f, 0.333333343f, 0.25f,
    0.2f, 0.166666672f, 0.142857149f, 0.125f
};

__global__ __launch_bounds__(BLOCK_THREADS) void bert_embed_kernel(
    const int* __restrict__ seq,          // [256*200]
    const float* __restrict__ tok_tab,    // [VOCAB,128]
    const float* __restrict__ gen_tab,    // [21,128]
    const float* __restrict__ pos_tab,    // [200,128]
    const int4* __restrict__ tgid,        // [VOCAB,8] as [VOCAB,2] int4
    const int* __restrict__ gcnt,         // [VOCAB]
    float* __restrict__ out)              // [256*200,128]
{
    const int warp = (blockIdx.x * BLOCK_THREADS + threadIdx.x) >> 5;
    const int lane = threadIdx.x & 31;
    const int half = lane >> 4;           // 0: token A, 1: token B
    const int ch   = lane & 15;           // 32B chunk index within row
    const int coff = ch * 8;              // float offset of chunk

    const uint64_t pol_st = mk_evict_first_policy();

    const int i = warp * 2 + half;        // this half's token index
    const int l = i % SEQ_L;
    const int t = __ldg(&seq[i]);         // uniform within each half

    // Per-half metadata (uniform within 16 lanes).
    const int  cnt = __ldg(&gcnt[t]);
    const int4 ga  = __ldg(&tgid[t * 2]);
    const int4 gb  = __ldg(&tgid[t * 2 + 1]);
    const int gid[MAX_G] = {ga.x, ga.y, ga.z, ga.w, gb.x, gb.y, gb.z, gb.w};

    // One v8 load covers both tokens' rows across the warp.
    const F8 tok = ldg_v8_evict_last(tok_tab + (size_t)t * 128 + coff);
    const F8 pos = ldg_v8(pos_tab + (size_t)l * 128 + coff);

    float s[8] = {0.f,0.f,0.f,0.f,0.f,0.f,0.f,0.f};
    #pragma unroll
    for (int g = 0; g < MAX_G; g++) {
        if (g < cnt) {                     // uniform within half
            const F8 ge = ldg_v8(gen_tab + (size_t)gid[g] * 128 + coff); // L1-hot
            #pragma unroll
            for (int q = 0; q < 8; q++) s[q] += ge.v[q];
        }
    }

    const float inv = c_inv[cnt];
    F8 o;
    #pragma unroll
    for (int q = 0; q < 8; q++) o.v[q] = tok.v[q] + pos.v[q] + s[q] * inv;

    stg_v8_evict_first(out + (size_t)i * 128 + coff, o, pol_st);
}

extern "C" void kernel_launch(void* const* d_in, const int* in_sizes, int n_in,
                              void* d_out, int out_size) {
    const int*   seq     = (const int*)d_in[0];
    const float* tok_tab = (const float*)d_in[1];
    const float* gen_tab = (const float*)d_in[2];
    const float* pos_tab = (const float*)d_in[3];
    const int4*  tgid    = (const int4*)d_in[4];
    const int*   gcnt    = (const int*)d_in[5];
    float*       out     = (float*)d_out;

    bert_embed_kernel<<<GRID_BLOCKS, BLOCK_THREADS>>>(
        seq, tok_tab, gen_tab, pos_tab, tgid, gcnt, out);
}

// round 17
// speedup vs baseline: 1.1361x; 1.1361x over previous
#include <cuda_runtime.h>
#include <cstdint>

// BERTEmbedding: out[b,l,:] = token_table[seq[b,l],:]
//                           + mean_{g<cnt}(genre_table[gids[seq[b,l],g],:])
//                           + pos_table[l,:]
//
// R17 (final): the thrice-reproduced best configuration (14.816us):
//  - warp per token, lane k owns float4 at dims [4k,4k+4): every global
//    access a coalesced 512B warp transaction.
//  - token-table gathers: ld.global.nc.L2::cache_hint (evict_last) — pins
//    the 51MB table in L2 across graph replays; the only lever that beat
//    the 15.07us plateau in 16 rounds.
//  - output: st.global.cs (streaming, evict-first) — keeps the write stream
//    from churning the table.
//  - exact reciprocal LUT for 1/cnt (cnt in 1..8).
//  - block size 128 (last untested knob: finer CTA granularity).

#define NUM_TOKENS (256 * 200)
#define SEQ_L 200
#define MAX_G 8
#define BLOCK_THREADS 128
#define GRID_BLOCKS (NUM_TOKENS / (BLOCK_THREADS / 32))   // 12800

__constant__ float c_inv[9] = {
    0.0f, 1.0f, 0.5f, 0.333333343f, 0.25f,
    0.2f, 0.166666672f, 0.142857149f, 0.125f
};

__device__ __forceinline__ uint64_t mk_evict_last_policy() {
    uint64_t pol;
    asm("createpolicy.fractional.L2::evict_last.b64 %0, 1.0;" : "=l"(pol));
    return pol;
}
__device__ __forceinline__ float4 ldg_hint(const float4* p, uint64_t pol) {
    float4 v;
    asm volatile("ld.global.nc.L2::cache_hint.v4.f32 {%0,%1,%2,%3}, [%4], %5;"
                 : "=f"(v.x), "=f"(v.y), "=f"(v.z), "=f"(v.w)
                 : "l"(p), "l"(pol));
    return v;
}
__device__ __forceinline__ void stg_cs(float4* p, float4 v) {
    asm volatile("st.global.cs.v4.f32 [%0], {%1,%2,%3,%4};"
                 :: "l"(p), "f"(v.x), "f"(v.y), "f"(v.z), "f"(v.w) : "memory");
}

__global__ __launch_bounds__(BLOCK_THREADS) void bert_embed_kernel(
    const int* __restrict__ seq,          // [256*200]
    const float4* __restrict__ tok_tab,   // [VOCAB,32]
    const float4* __restrict__ gen_tab,   // [21,32]
    const float4* __restrict__ pos_tab,   // [200,32]
    const int4* __restrict__ tgid,        // [VOCAB,8] as [VOCAB,2] int4
    const int* __restrict__ gcnt,         // [VOCAB]
    float4* __restrict__ out)             // [256*200,32]
{
    const int warp = (blockIdx.x * BLOCK_THREADS + threadIdx.x) >> 5;
    const int lane = threadIdx.x & 31;

    const uint64_t pol = mk_evict_last_policy();

    const int l = warp % SEQ_L;
    const int t = __ldg(&seq[warp]);               // warp-uniform

    // Independent level-2 loads, back-to-back for MLP.
    const int    cnt = __ldg(&gcnt[t]);            // warp-uniform
    const int4   ga  = __ldg(&tgid[t * 2]);        // warp-uniform
    const int4   gb  = __ldg(&tgid[t * 2 + 1]);    // warp-uniform
    const float4 tok = ldg_hint(&tok_tab[(size_t)t * 32 + lane], pol);  // L2-pinned
    const float4 pos = __ldg(&pos_tab[l * 32 + lane]);

    const int gid[MAX_G] = {ga.x, ga.y, ga.z, ga.w, gb.x, gb.y, gb.z, gb.w};

    float4 s = make_float4(0.f, 0.f, 0.f, 0.f);
    #pragma unroll
    for (int g = 0; g < MAX_G; g++) {
        if (g < cnt) {                              // warp-uniform predicate
            const float4 ge = __ldg(&gen_tab[gid[g] * 32 + lane]);  // L1-hot
            s.x += ge.x; s.y += ge.y; s.z += ge.z; s.w += ge.w;
        }
    }

    const float inv = c_inv[cnt];                   // exact reciprocal
    float4 o;
    o.x = tok.x + pos.x + s.x * inv;
    o.y = tok.y + pos.y + s.y * inv;
    o.z = tok.z + pos.z + s.z * inv;
    o.w = tok.w + pos.w + s.w * inv;

    // Streaming store: evict-first, don't churn the table out of L2.
    stg_cs(&out[(size_t)warp * 32 + lane], o);
}

extern "C" void kernel_launch(void* const* d_in, const int* in_sizes, int n_in,
                              void* d_out, int out_size) {
    const int*    seq     = (const int*)d_in[0];
    const float4* tok_tab = (const float4*)d_in[1];
    const float4* gen_tab = (const float4*)d_in[2];
    const float4* pos_tab = (const float4*)d_in[3];
    const int4*   tgid    = (const int4*)d_in[4];
    const int*    gcnt    = (const int*)d_in[5];
    float4*       out     = (float4*)d_out;

    bert_embed_kernel<<<GRID_BLOCKS, BLOCK_THREADS>>>(
        seq, tok_tab, gen_tab, pos_tab, tgid, gcnt, out);
}